// round 14
// baseline (speedup 1.0000x reference)
#include <cuda_runtime.h>
#include <cuda_fp16.h>

#define NN 100000
#define FF 256
#define DD 128
#define MM 10
#define BB 32768
#define KK 32

// ---------------- scratch (device globals; no allocation) ----------------
__device__ __align__(16) __half g_feat_h[NN * FF];    // 51.2 MB feature fp16
__device__ __align__(16) __half g_WhT[DD * FF];       // Wemb transposed [n][k] fp16
__device__ __align__(16) __half g_W1hT[DD * DD];      // (W1_top+W1_bot) transposed [n][k] fp16
__device__ __align__(16) __half g_flow_h[NN * DD];    // 25.6 MB flow_all fp16
__device__ __align__(16) __half g_agg_h[BB * DD];     // 8 MB agg fp16
__device__ float g_score[NN];
__device__ __align__(16) float g_char[MM * DD];
__device__ __align__(16) float g_cefeat[MM * FF];
__device__ float g_rowsum[MM];
__device__ __align__(16) float g_at[2 * DD];
__device__ __align__(16) float g_bb[MM * DD];

struct Ptrs {
    const float* wemb;
    const float* wchar;
    const float* lin1w;
    const int*   catr;
    const int*   catn;
    const int*   pa;
};
__device__ Ptrs g_ptrs;

// ---------------- K0: probe + zero + weight conversion (merged) ----------------
__global__ void fixup2_kernel(const void* s0, const void* s1, const void* s2,
                              const void* s3, const void* s4, const void* s5,
                              const void* s6) {
    const unsigned* u = (const unsigned*)s0;
    bool intlike = true;
    for (int i = 0; i < 64; i++) {
        if (u[i] >= 100000u) { intlike = false; break; }
    }
    const float* wemb  = intlike ? (const float*)s4 : (const float*)s0;
    const float* lin1w = intlike ? (const float*)s6 : (const float*)s2;
    const int b = blockIdx.x, t = threadIdx.x;
    if (b == 192) {
        if (t == 0) {
            Ptrs p;
            if (intlike) {
                p.catr = (const int*)s1;  p.catn = (const int*)s2;  p.pa = (const int*)s3;
                p.wemb = (const float*)s4; p.wchar = (const float*)s5; p.lin1w = (const float*)s6;
            } else {
                p.wemb = (const float*)s0; p.wchar = (const float*)s1; p.lin1w = (const float*)s2;
                p.catr = (const int*)s4;  p.catn = (const int*)s5;  p.pa = (const int*)s6;
            }
            g_ptrs = p;
        }
        for (int i = t; i < MM * FF; i += 256) g_cefeat[i] = 0.f;
        for (int i = t; i < MM * DD; i += 256) { g_char[i] = 0.f; g_bb[i] = 0.f; }
        for (int i = t; i < 2 * DD; i += 256) g_at[i] = 0.f;
        if (t < MM) g_rowsum[t] = 0.f;
    } else {
        const int i = b * 256 + t;
        if (i < FF * DD) {
            const int k = i / DD, n = i % DD;
            g_WhT[n * FF + k] = __float2half(wemb[i]);
        } else {
            const int j = i - FF * DD;
            const int k = j / DD, n = j % DD;
            g_W1hT[n * DD + k] = __float2half(lin1w[k * DD + n] + lin1w[(DD + k) * DD + n]);
        }
    }
}

// ---------------- K1: adj@feature + rowsum + fp16 copy ----------------
// R13 WIN structure; adj operands now loaded as explicit float4 LDS.128
// (was 10 scalar LDS.32 per element -> instr/elt ~23 -> ~15.5; kernel is issue-bound).
__global__ __launch_bounds__(256) void adjfeat_kernel(const float* __restrict__ adj,
                                                      const float* __restrict__ feat) {
    __shared__ __align__(16) float adj_s[MM][256];
    const int n0  = blockIdx.x * 256;
    const int tid = threadIdx.x;
    int limit = NN - n0;
    if (limit > 256) limit = 256;
    for (int m = 0; m < MM; m++)
        if (tid < limit) adj_s[m][tid] = adj[(size_t)m * NN + n0 + tid];
    __syncthreads();
    float acc[MM];
#pragma unroll
    for (int m = 0; m < MM; m++) acc[m] = 0.f;
    int j = 0;
    for (; j + 8 <= limit; j += 8) {
        float v[8];
#pragma unroll
        for (int u = 0; u < 8; u++)
            v[u] = feat[(size_t)(n0 + j + u) * FF + tid];
#pragma unroll
        for (int u = 0; u < 8; u++)
            g_feat_h[(size_t)(n0 + j + u) * FF + tid] = __float2half(v[u]);
#pragma unroll
        for (int m = 0; m < MM; m++) {
            const float4 a0 = *(const float4*)&adj_s[m][j];
            const float4 a1 = *(const float4*)&adj_s[m][j + 4];
            acc[m] += a0.x * v[0] + a0.y * v[1] + a0.z * v[2] + a0.w * v[3]
                    + a1.x * v[4] + a1.y * v[5] + a1.z * v[6] + a1.w * v[7];
        }
    }
    for (; j < limit; j++) {
        const float v = feat[(size_t)(n0 + j) * FF + tid];
        g_feat_h[(size_t)(n0 + j) * FF + tid] = __float2half(v);
#pragma unroll
        for (int m = 0; m < MM; m++) acc[m] += adj_s[m][j] * v;
    }
#pragma unroll
    for (int m = 0; m < MM; m++) atomicAdd(&g_cefeat[m * FF + tid], acc[m]);
    const int warp = tid >> 5, lane = tid & 31;
    for (int m = warp; m < MM; m += 8) {
        float s = 0.f;
        for (int jj = lane; jj < limit; jj += 32) s += adj_s[m][jj];
#pragma unroll
        for (int o = 16; o; o >>= 1) s += __shfl_xor_sync(0xffffffffu, s, o);
        if (lane == 0) atomicAdd(&g_rowsum[m], s);
    }
}

// ---------------- K2: char[m][d] += ce_feat[m][k0:k0+32] @ W[k0:k0+32, d] ---------------
__global__ __launch_bounds__(128) void char_kernel2(const float* __restrict__ bias) {
    __shared__ float ce[32];
    const int m  = blockIdx.x >> 3;
    const int k0 = (blockIdx.x & 7) * 32;
    const int d  = threadIdx.x;
    if (d < 32) ce[d] = g_cefeat[m * FF + k0 + d];
    __syncthreads();
    const float* W = g_ptrs.wemb;
    float s = 0.f;
#pragma unroll
    for (int k = 0; k < 32; k++) s += ce[k] * W[(size_t)(k0 + k) * DD + d];
    if (k0 == 0) s += g_rowsum[m] * bias[d];
    atomicAdd(&g_char[m * DD + d], s);
}

// ---------------- K5: fp16 tensor GEMM, 3-stage pipeline + B-fragment prefetch ---------
// Slot #3 -> profiled. R13 signature (tensor 25/L1 68/issue 21, occ 22.6) = stall-bound
// on LDSM->HMMA RAW. bn/bc double-buffer breaks the dependency for 6 of 8 groups/chunk.
#define STG_B (128 * 40 * 2)   // one stage of A or B: 10240 bytes
#define GEMM_SMEM (6 * STG_B + 640 * 4)
__global__ __launch_bounds__(256) void gemm_fused(const float* __restrict__ bias,
                                                  const float* __restrict__ adj,
                                                  const float* __restrict__ att1w,
                                                  const float* __restrict__ att1b) {
    extern __shared__ __align__(16) char dsm[];
    float* att_s  = (float*)(dsm + 6 * STG_B);
    float* bias_s = att_s + DD;
    float* ch_s0  = bias_s + DD;
    float* ch_s1  = ch_s0 + DD;
    float* sc     = ch_s1 + DD;
    const int tid  = threadIdx.x;
    const int warp = tid >> 5, lane = tid & 31;
    const int gid  = lane >> 2, tig = lane & 3;
    const int wm   = warp & 3, wn = warp >> 2;     // 4 m-warps x 2 n-warps
    const int row0 = blockIdx.x * 128;
    if (tid < DD) {
        att_s[tid]  = att1w[tid];
        bias_s[tid] = bias[tid];
        ch_s0[tid]  = g_char[tid];
        ch_s1[tid]  = g_char[DD + tid];
        sc[tid]     = 0.f;
    }

    float c[2][8][4];
#pragma unroll
    for (int mt = 0; mt < 2; mt++)
#pragma unroll
        for (int nt = 0; nt < 8; nt++)
#pragma unroll
            for (int j = 0; j < 4; j++) c[mt][nt][j] = 0.f;

    const unsigned As_sh = (unsigned)__cvta_generic_to_shared(dsm);
    const unsigned Bs_sh = As_sh + 3 * STG_B;
    const int srow = tid >> 1;
    const int scol = (tid & 1) * 16;
    const int a_sz = (row0 + srow < NN) ? 16 : 0;
    const unsigned st_off = srow * 80 + scol * 2;
    auto ldAB = [&](int s, int kt) {
#pragma unroll
        for (int p = 0; p < 2; p++) {
            const unsigned da = As_sh + s * STG_B + st_off + p * 16;
            const __half* sa = g_feat_h + (size_t)(row0 + srow) * FF + kt + scol + p * 8;
            asm volatile("cp.async.ca.shared.global [%0], [%1], 16, %2;"
                         :: "r"(da), "l"(sa), "r"(a_sz));
            const unsigned db = Bs_sh + s * STG_B + st_off + p * 16;
            const __half* sb = g_WhT + (size_t)srow * FF + kt + scol + p * 8;
            asm volatile("cp.async.ca.shared.global [%0], [%1], 16;"
                         :: "r"(db), "l"(sb));
        }
    };

    unsigned a_off[2];
#pragma unroll
    for (int mt = 0; mt < 2; mt++) {
        const unsigned r  = wm * 32 + mt * 16 + (lane & 15);
        const unsigned cc = (lane >> 4) * 8;
        a_off[mt] = r * 80 + cc * 2;
    }
    unsigned b_off[4];
#pragma unroll
    for (int ntp = 0; ntp < 4; ntp++) {
        const unsigned r  = wn * 64 + ntp * 16 + (lane & 7) + ((lane >> 4) << 3);
        const unsigned cc = ((lane >> 3) & 1) * 8;
        b_off[ntp] = r * 80 + cc * 2;
    }

    // 3-stage prologue: 2 chunks in flight
    ldAB(0, 0);
    asm volatile("cp.async.commit_group;");
    ldAB(1, 32);
    asm volatile("cp.async.commit_group;");

    int cur = 0;
    for (int it = 0; it < FF / 32; it++) {
        if (it < FF / 32 - 1) {
            asm volatile("cp.async.wait_group 1;");
        } else {
            asm volatile("cp.async.wait_group 0;");
        }
        __syncthreads();
        if (it + 2 < FF / 32) {
            int nstage = cur + 2;
            if (nstage >= 3) nstage -= 3;
            ldAB(nstage, (it + 2) * 32);
            asm volatile("cp.async.commit_group;");
        }
#pragma unroll
        for (int kk = 0; kk < 32; kk += 16) {
            unsigned a[2][4];
#pragma unroll
            for (int mt = 0; mt < 2; mt++) {
                const unsigned addr = As_sh + cur * STG_B + a_off[mt] + kk * 2;
                asm volatile("ldmatrix.sync.aligned.m8n8.x4.shared.b16 {%0,%1,%2,%3}, [%4];"
                             : "=r"(a[mt][0]), "=r"(a[mt][1]), "=r"(a[mt][2]), "=r"(a[mt][3])
                             : "r"(addr));
            }
            // prefetch pipeline: bc = current B fragments, bn = next
            unsigned bc[4];
            {
                const unsigned addr = Bs_sh + cur * STG_B + b_off[0] + kk * 2;
                asm volatile("ldmatrix.sync.aligned.m8n8.x4.shared.b16 {%0,%1,%2,%3}, [%4];"
                             : "=r"(bc[0]), "=r"(bc[1]), "=r"(bc[2]), "=r"(bc[3])
                             : "r"(addr));
            }
#pragma unroll
            for (int ntp = 0; ntp < 4; ntp++) {
                unsigned bn[4];
                if (ntp < 3) {
                    const unsigned addr = Bs_sh + cur * STG_B + b_off[ntp + 1] + kk * 2;
                    asm volatile("ldmatrix.sync.aligned.m8n8.x4.shared.b16 {%0,%1,%2,%3}, [%4];"
                                 : "=r"(bn[0]), "=r"(bn[1]), "=r"(bn[2]), "=r"(bn[3])
                                 : "r"(addr));
                }
#pragma unroll
                for (int mt = 0; mt < 2; mt++) {
                    asm volatile(
                        "mma.sync.aligned.m16n8k16.row.col.f32.f16.f16.f32 "
                        "{%0,%1,%2,%3}, {%4,%5,%6,%7}, {%8,%9}, {%0,%1,%2,%3};"
                        : "+f"(c[mt][ntp * 2][0]), "+f"(c[mt][ntp * 2][1]),
                          "+f"(c[mt][ntp * 2][2]), "+f"(c[mt][ntp * 2][3])
                        : "r"(a[mt][0]), "r"(a[mt][1]), "r"(a[mt][2]), "r"(a[mt][3]),
                          "r"(bc[0]), "r"(bc[1]));
                    asm volatile(
                        "mma.sync.aligned.m16n8k16.row.col.f32.f16.f16.f32 "
                        "{%0,%1,%2,%3}, {%4,%5,%6,%7}, {%8,%9}, {%0,%1,%2,%3};"
                        : "+f"(c[mt][ntp * 2 + 1][0]), "+f"(c[mt][ntp * 2 + 1][1]),
                          "+f"(c[mt][ntp * 2 + 1][2]), "+f"(c[mt][ntp * 2 + 1][3])
                        : "r"(a[mt][0]), "r"(a[mt][1]), "r"(a[mt][2]), "r"(a[mt][3]),
                          "r"(bc[2]), "r"(bc[3]));
                }
                if (ntp < 3) {
                    bc[0] = bn[0]; bc[1] = bn[1]; bc[2] = bn[2]; bc[3] = bn[3];
                }
            }
        }
        if (++cur == 3) cur = 0;
    }

    // epilogue: bias + attribute mix, fp16 flow store, partial score -> smem atomics
#pragma unroll
    for (int mt = 0; mt < 2; mt++) {
        const int rl1 = wm * 32 + mt * 16 + gid;
        const int rl2 = rl1 + 8;
        const int r1 = row0 + rl1, r2 = row0 + rl2;
        float a0r1 = 0.f, a1r1 = 0.f, a0r2 = 0.f, a1r2 = 0.f;
        if (r1 < NN) { a0r1 = adj[r1]; a1r1 = adj[NN + r1]; }
        if (r2 < NN) { a0r2 = adj[r2]; a1r2 = adj[NN + r2]; }
        float s1 = 0.f, s2 = 0.f;
#pragma unroll
        for (int nt = 0; nt < 8; nt++) {
            const int col = wn * 64 + nt * 8 + tig * 2;
            const float ch0a = ch_s0[col], ch0b = ch_s0[col + 1];
            const float ch1a = ch_s1[col], ch1b = ch_s1[col + 1];
            const float ba = bias_s[col], bbv = bias_s[col + 1];
            const float v1a = 0.5f * (c[mt][nt][0] + ba  + a0r1 * ch0a + a1r1 * ch1a);
            const float v1b = 0.5f * (c[mt][nt][1] + bbv + a0r1 * ch0b + a1r1 * ch1b);
            const float v2a = 0.5f * (c[mt][nt][2] + ba  + a0r2 * ch0a + a1r2 * ch1a);
            const float v2b = 0.5f * (c[mt][nt][3] + bbv + a0r2 * ch0b + a1r2 * ch1b);
            if (r1 < NN)
                *(__half2*)&g_flow_h[(size_t)r1 * DD + col] = __floats2half2_rn(v1a, v1b);
            if (r2 < NN)
                *(__half2*)&g_flow_h[(size_t)r2 * DD + col] = __floats2half2_rn(v2a, v2b);
            s1 += v1a * att_s[col] + v1b * att_s[col + 1];
            s2 += v2a * att_s[col] + v2b * att_s[col + 1];
        }
        s1 += __shfl_xor_sync(0xffffffffu, s1, 1);
        s1 += __shfl_xor_sync(0xffffffffu, s1, 2);
        s2 += __shfl_xor_sync(0xffffffffu, s2, 1);
        s2 += __shfl_xor_sync(0xffffffffu, s2, 2);
        if (tig == 0) {
            atomicAdd(&sc[rl1], s1);
            atomicAdd(&sc[rl2], s2);
        }
    }
    __syncthreads();
    if (tid < 128) {
        const int r = row0 + tid;
        if (r < NN) g_score[r] = sc[tid] + att1b[0];
    }
}

// ---------------- K3: at / bb halves of the character GEMV (k-split x4) ---------------
__global__ __launch_bounds__(128) void lat_kernel2() {
    __shared__ float ch[32];
    const int t  = blockIdx.x >> 2;
    const int k0 = (blockIdx.x & 3) * 32;
    const int d  = threadIdx.x;
    const float* Wc = g_ptrs.wchar;
    const int m = (t < 2) ? t : (t - 2);
    if (d < 32) ch[d] = g_char[m * DD + k0 + d];
    __syncthreads();
    float s = 0.f;
    if (t < 2) {
#pragma unroll
        for (int i = 0; i < 32; i++) s += ch[i] * Wc[(size_t)(k0 + i) * DD + d];
        atomicAdd(&g_at[t * DD + d], s);
    } else {
#pragma unroll
        for (int i = 0; i < 32; i++) s += ch[i] * Wc[(size_t)(DD + k0 + i) * DD + d];
        atomicAdd(&g_bb[m * DD + d], s);
    }
}

// ---------------- K6: per-row gather + softmax + weighted sum -> fp16 agg ---------------
__global__ __launch_bounds__(256) void agg_kernel(const int* __restrict__ history) {
    const int warp = threadIdx.x >> 5, lane = threadIdx.x & 31;
    const int b = blockIdx.x * 8 + warp;
    const int h = history[b * KK + lane];
    const float s = g_score[h];
    float mx = s;
#pragma unroll
    for (int o = 16; o; o >>= 1) mx = fmaxf(mx, __shfl_xor_sync(0xffffffffu, mx, o));
    const float e = expf(s - mx);
    float sum = e;
#pragma unroll
    for (int o = 16; o; o >>= 1) sum += __shfl_xor_sync(0xffffffffu, sum, o);
    const float att = e / sum;
    float4 acc = make_float4(0.f, 0.f, 0.f, 0.f);
    const uint2* fa = (const uint2*)g_flow_h;
#pragma unroll
    for (int k = 0; k < KK; k++) {
        const int   idx = __shfl_sync(0xffffffffu, h, k);
        const float w   = __shfl_sync(0xffffffffu, att, k);
        const uint2 f = fa[idx * 32 + lane];
        const float2 p0 = __half22float2(*(const __half2*)&f.x);
        const float2 p1 = __half22float2(*(const __half2*)&f.y);
        acc.x += w * p0.x; acc.y += w * p0.y; acc.z += w * p1.x; acc.w += w * p1.y;
    }
    __half2 h0 = __floats2half2_rn(acc.x, acc.y);
    __half2 h1 = __floats2half2_rn(acc.z, acc.w);
    uint2 st;
    st.x = *(unsigned*)&h0;
    st.y = *(unsigned*)&h1;
    *(uint2*)&g_agg_h[(size_t)b * DD + lane * 4] = st;
}

// ---------------- K7: fp16 tensor out-GEMM + fused sigmoid-Lat + relu/Lat-dot -----------
__global__ __launch_bounds__(256) void outpred_kernel(const float* __restrict__ lin1b,
                                                      float* __restrict__ out) {
    __shared__ __half As[128][40];
    __shared__ __half Bs[128][40];
    __shared__ float Lat_s[2 * MM * DD];
    __shared__ float lb_s[DD];
    const int*   catr = g_ptrs.catr;
    const int*   catn = g_ptrs.catn;
    const int*   pav  = g_ptrs.pa;
    const int tid  = threadIdx.x;
    const int warp = tid >> 5, lane = tid & 31;
    const int gid  = lane >> 2, tig = lane & 3;
    const int row0 = blockIdx.x * 128;
    for (int i = tid; i < 2 * MM * DD; i += 256) {
        const int d  = i & 127;
        const int p  = (i >> 7) % MM;
        const int cc = i / (MM * DD);
        Lat_s[i] = 1.f / (1.f + expf(-(g_at[cc * DD + d] + g_bb[p * DD + d])));
    }
    if (tid < DD) lb_s[tid] = lin1b[tid];

    float c[16][4];
#pragma unroll
    for (int nt = 0; nt < 16; nt++)
#pragma unroll
        for (int j = 0; j < 4; j++) c[nt][j] = 0.f;

    const int arow = tid >> 1;
    const int acol = (tid & 1) * 16;
#pragma unroll
    for (int kt = 0; kt < DD; kt += 32) {
        *(uint4*)&As[arow][acol]     = *(const uint4*)&g_agg_h[(size_t)(row0 + arow) * DD + kt + acol];
        *(uint4*)&As[arow][acol + 8] = *(const uint4*)&g_agg_h[(size_t)(row0 + arow) * DD + kt + acol + 8];
        *(uint4*)&Bs[arow][acol]     = *(const uint4*)&g_W1hT[(size_t)arow * DD + kt + acol];
        *(uint4*)&Bs[arow][acol + 8] = *(const uint4*)&g_W1hT[(size_t)arow * DD + kt + acol + 8];
        __syncthreads();
#pragma unroll
        for (int kk = 0; kk < 32; kk += 16) {
            const unsigned a0 = *(const unsigned*)&As[warp * 16 + gid    ][kk + tig * 2];
            const unsigned a1 = *(const unsigned*)&As[warp * 16 + gid + 8][kk + tig * 2];
            const unsigned a2 = *(const unsigned*)&As[warp * 16 + gid    ][kk + tig * 2 + 8];
            const unsigned a3 = *(const unsigned*)&As[warp * 16 + gid + 8][kk + tig * 2 + 8];
#pragma unroll
            for (int nt = 0; nt < 16; nt++) {
                const unsigned b0 = *(const unsigned*)&Bs[nt * 8 + gid][kk + tig * 2];
                const unsigned b1 = *(const unsigned*)&Bs[nt * 8 + gid][kk + tig * 2 + 8];
                asm volatile(
                    "mma.sync.aligned.m16n8k16.row.col.f32.f16.f16.f32 "
                    "{%0,%1,%2,%3}, {%4,%5,%6,%7}, {%8,%9}, {%0,%1,%2,%3};"
                    : "+f"(c[nt][0]), "+f"(c[nt][1]), "+f"(c[nt][2]), "+f"(c[nt][3])
                    : "r"(a0), "r"(a1), "r"(a2), "r"(a3), "r"(b0), "r"(b1));
            }
        }
        __syncthreads();
    }

    const int r1 = row0 + warp * 16 + gid;
    const int r2 = r1 + 8;
    const int p1_ = pav[r1], p2_ = pav[r2];
    const float* Lr1 = &Lat_s[(catr[r1] * MM + p1_) * DD];
    const float* Ln1 = &Lat_s[(catn[r1] * MM + p1_) * DD];
    const float* Lr2 = &Lat_s[(catr[r2] * MM + p2_) * DD];
    const float* Ln2 = &Lat_s[(catn[r2] * MM + p2_) * DD];
    float sr1 = 0.f, sn1 = 0.f, sr2 = 0.f, sn2 = 0.f;
#pragma unroll
    for (int nt = 0; nt < 16; nt++) {
        const int col = nt * 8 + tig * 2;
        const float b0 = lb_s[col], b1 = lb_s[col + 1];
        const float o0 = fmaxf(c[nt][0] + b0, 0.f);
        const float o1 = fmaxf(c[nt][1] + b1, 0.f);
        const float o2 = fmaxf(c[nt][2] + b0, 0.f);
        const float o3 = fmaxf(c[nt][3] + b1, 0.f);
        sr1 += o0 * Lr1[col] + o1 * Lr1[col + 1];
        sn1 += o0 * Ln1[col] + o1 * Ln1[col + 1];
        sr2 += o2 * Lr2[col] + o3 * Lr2[col + 1];
        sn2 += o2 * Ln2[col] + o3 * Ln2[col + 1];
    }
#pragma unroll
    for (int o = 1; o < 4; o <<= 1) {
        sr1 += __shfl_xor_sync(0xffffffffu, sr1, o);
        sn1 += __shfl_xor_sync(0xffffffffu, sn1, o);
        sr2 += __shfl_xor_sync(0xffffffffu, sr2, o);
        sn2 += __shfl_xor_sync(0xffffffffu, sn2, o);
    }
    if (tig == 0) {
        out[r1]      = sr1;
        out[BB + r1] = sn1;
        out[r2]      = sr2;
        out[BB + r2] = sn2;
    }
}

// ---------------- host ----------------
extern "C" void kernel_launch(void* const* d_in, const int* in_sizes, int n_in,
                              void* d_out, int out_size) {
    const float* feat = nullptr;
    const float* adj  = nullptr;
    const int*   hist = nullptr;
    const float* b1   = nullptr;
    const void*  s32[8] = {nullptr};
    int n32 = 0;
    const float* s128[4] = {nullptr};
    int n128 = 0;

    for (int i = 0; i < n_in; i++) {
        const int sz = in_sizes[i];
        if (sz == NN * FF)      feat = (const float*)d_in[i];
        else if (sz == MM * NN) adj  = (const float*)d_in[i];
        else if (sz == BB * KK) hist = (const int*)d_in[i];
        else if (sz == BB)      { if (n32 < 8)  s32[n32++]  = d_in[i]; }
        else if (sz == DD)      { if (n128 < 4) s128[n128++] = (const float*)d_in[i]; }
        else if (sz == 1)       b1 = (const float*)d_in[i];
    }
    const float* bemb  = s128[0];
    const float* att1w = s128[1];
    const float* lin1b = s128[2];

    cudaFuncSetAttribute(gemm_fused, cudaFuncAttributeMaxDynamicSharedMemorySize,
                         GEMM_SMEM);

    fixup2_kernel<<<193, 256>>>(s32[0], s32[1], s32[2], s32[3], s32[4], s32[5], s32[6]);
    adjfeat_kernel<<<(NN + 255) / 256, 256>>>(adj, feat);
    char_kernel2<<<MM * 8, 128>>>(bemb);
    gemm_fused<<<(NN + 127) / 128, 256, GEMM_SMEM>>>(bemb, adj, att1w, b1);  // slot #3
    lat_kernel2<<<(MM + 2) * 4, 128>>>();
    agg_kernel<<<BB / 8, 256>>>(hist);
    outpred_kernel<<<BB / 128, 256>>>(lin1b, (float*)d_out);
}

// round 15
// speedup vs baseline: 1.0458x; 1.0458x over previous
#include <cuda_runtime.h>
#include <cuda_fp16.h>

#define NN 100000
#define FF 256
#define DD 128
#define MM 10
#define BB 32768
#define KK 32

// ---------------- scratch (device globals; no allocation) ----------------
__device__ __align__(16) __half g_feat_h[NN * FF];    // 51.2 MB feature fp16
__device__ __align__(16) __half g_WhT[DD * FF];       // Wemb transposed [n][k] fp16
__device__ __align__(16) __half g_W1hT[DD * DD];      // (W1_top+W1_bot) transposed [n][k] fp16
__device__ __align__(16) __half g_flow_h[NN * DD];    // 25.6 MB flow_all fp16
__device__ __align__(16) __half g_agg_h[BB * DD];     // 8 MB agg fp16
__device__ float g_score[NN];
__device__ __align__(16) float g_char[MM * DD];
__device__ __align__(16) float g_cefeat[MM * FF];
__device__ float g_rowsum[MM];
__device__ __align__(16) float g_at[2 * DD];
__device__ __align__(16) float g_bb[MM * DD];

struct Ptrs {
    const float* wemb;
    const float* wchar;
    const float* lin1w;
    const int*   catr;
    const int*   catn;
    const int*   pa;
};
__device__ Ptrs g_ptrs;

__device__ __forceinline__ bool probe_intlike(const void* s0) {
    const unsigned* u = (const unsigned*)s0;
    bool intlike = true;
    for (int i = 0; i < 64; i++) {
        if (u[i] >= 100000u) { intlike = false; break; }
    }
    return intlike;
}

// ---------------- K0a: probe input ordering -> g_ptrs ----------------
__global__ void probe_kernel(const void* s0, const void* s1, const void* s2,
                             const void* s3, const void* s4, const void* s5,
                             const void* s6) {
    if (threadIdx.x == 0) {
        Ptrs p;
        if (probe_intlike(s0)) {
            p.catr = (const int*)s1;  p.catn = (const int*)s2;  p.pa = (const int*)s3;
            p.wemb = (const float*)s4; p.wchar = (const float*)s5; p.lin1w = (const float*)s6;
        } else {
            p.wemb = (const float*)s0; p.wchar = (const float*)s1; p.lin1w = (const float*)s2;
            p.catr = (const int*)s4;  p.catn = (const int*)s5;  p.pa = (const int*)s6;
        }
        g_ptrs = p;
    }
}

// ---------------- K0b: zero accumulators ----------------
__global__ void zero_kernel() {
    const int t = threadIdx.x;
    for (int i = t; i < MM * FF; i += 256) g_cefeat[i] = 0.f;
    for (int i = t; i < MM * DD; i += 256) { g_char[i] = 0.f; g_bb[i] = 0.f; }
    for (int i = t; i < 2 * DD; i += 256) g_at[i] = 0.f;
    if (t < MM) g_rowsum[t] = 0.f;
}

// ---------------- K0c: weight conversion (derives probe locally) ----------------
__global__ void wcvt_kernel(const void* s0, const void* s2, const void* s4,
                            const void* s6) {
    const bool intlike = probe_intlike(s0);
    const float* wemb  = intlike ? (const float*)s4 : (const float*)s0;
    const float* lin1w = intlike ? (const float*)s6 : (const float*)s2;
    const int i = blockIdx.x * 256 + threadIdx.x;
    if (i < FF * DD) {
        const int k = i / DD, n = i % DD;
        g_WhT[n * FF + k] = __float2half(wemb[i]);
    } else if (i < FF * DD + DD * DD) {
        const int j = i - FF * DD;
        const int k = j / DD, n = j % DD;
        g_W1hT[n * DD + k] = __float2half(lin1w[k * DD + n] + lin1w[(DD + k) * DD + n]);
    }
}

// ---------------- K1 (slot #3, profiled): adj@feature + rowsum + fp16 copy -------------
// R13 WIN form (scalar adj_s reads — R14's float4 variant regressed), MLP deepened
// 8 -> 16: 16 outstanding LDGs to push DRAM 41% -> ~55% (latency still exposed at 8).
__global__ __launch_bounds__(256) void adjfeat_kernel(const float* __restrict__ adj,
                                                      const float* __restrict__ feat) {
    __shared__ float adj_s[MM][256];
    const int n0  = blockIdx.x * 256;
    const int tid = threadIdx.x;
    int limit = NN - n0;
    if (limit > 256) limit = 256;
    for (int m = 0; m < MM; m++)
        if (tid < limit) adj_s[m][tid] = adj[(size_t)m * NN + n0 + tid];
    __syncthreads();
    float acc[MM];
#pragma unroll
    for (int m = 0; m < MM; m++) acc[m] = 0.f;
    int j = 0;
    for (; j + 16 <= limit; j += 16) {
        float v[16];
#pragma unroll
        for (int u = 0; u < 16; u++)
            v[u] = feat[(size_t)(n0 + j + u) * FF + tid];
#pragma unroll
        for (int u = 0; u < 16; u++)
            g_feat_h[(size_t)(n0 + j + u) * FF + tid] = __float2half(v[u]);
#pragma unroll
        for (int u = 0; u < 16; u++)
#pragma unroll
            for (int m = 0; m < MM; m++) acc[m] += adj_s[m][j + u] * v[u];
    }
    for (; j < limit; j++) {
        const float v = feat[(size_t)(n0 + j) * FF + tid];
        g_feat_h[(size_t)(n0 + j) * FF + tid] = __float2half(v);
#pragma unroll
        for (int m = 0; m < MM; m++) acc[m] += adj_s[m][j] * v;
    }
#pragma unroll
    for (int m = 0; m < MM; m++) atomicAdd(&g_cefeat[m * FF + tid], acc[m]);
    const int warp = tid >> 5, lane = tid & 31;
    for (int m = warp; m < MM; m += 8) {
        float s = 0.f;
        for (int jj = lane; jj < limit; jj += 32) s += adj_s[m][jj];
#pragma unroll
        for (int o = 16; o; o >>= 1) s += __shfl_xor_sync(0xffffffffu, s, o);
        if (lane == 0) atomicAdd(&g_rowsum[m], s);
    }
}

// ---------------- K2: char[m][d] += ce_feat[m][k0:k0+32] @ W[k0:k0+32, d] ---------------
__global__ __launch_bounds__(128) void char_kernel2(const float* __restrict__ bias) {
    __shared__ float ce[32];
    const int m  = blockIdx.x >> 3;
    const int k0 = (blockIdx.x & 7) * 32;
    const int d  = threadIdx.x;
    if (d < 32) ce[d] = g_cefeat[m * FF + k0 + d];
    __syncthreads();
    const float* W = g_ptrs.wemb;
    float s = 0.f;
#pragma unroll
    for (int k = 0; k < 32; k++) s += ce[k] * W[(size_t)(k0 + k) * DD + d];
    if (k0 == 0) s += g_rowsum[m] * bias[d];
    atomicAdd(&g_char[m * DD + d], s);
}

// ---------------- K5: fp16 tensor GEMM, 3-stage pipeline (exact R13 WIN form) ----------
#define STG_B (128 * 40 * 2)   // one stage of A or B: 10240 bytes
#define GEMM_SMEM (6 * STG_B + 640 * 4)
__global__ __launch_bounds__(256) void gemm_fused(const float* __restrict__ bias,
                                                  const float* __restrict__ adj,
                                                  const float* __restrict__ att1w,
                                                  const float* __restrict__ att1b) {
    extern __shared__ __align__(16) char dsm[];
    float* att_s  = (float*)(dsm + 6 * STG_B);
    float* bias_s = att_s + DD;
    float* ch_s0  = bias_s + DD;
    float* ch_s1  = ch_s0 + DD;
    float* sc     = ch_s1 + DD;
    const int tid  = threadIdx.x;
    const int warp = tid >> 5, lane = tid & 31;
    const int gid  = lane >> 2, tig = lane & 3;
    const int wm   = warp & 3, wn = warp >> 2;     // 4 m-warps x 2 n-warps
    const int row0 = blockIdx.x * 128;
    if (tid < DD) {
        att_s[tid]  = att1w[tid];
        bias_s[tid] = bias[tid];
        ch_s0[tid]  = g_char[tid];
        ch_s1[tid]  = g_char[DD + tid];
        sc[tid]     = 0.f;
    }

    float c[2][8][4];
#pragma unroll
    for (int mt = 0; mt < 2; mt++)
#pragma unroll
        for (int nt = 0; nt < 8; nt++)
#pragma unroll
            for (int j = 0; j < 4; j++) c[mt][nt][j] = 0.f;

    const unsigned As_sh = (unsigned)__cvta_generic_to_shared(dsm);
    const unsigned Bs_sh = As_sh + 3 * STG_B;
    const int srow = tid >> 1;
    const int scol = (tid & 1) * 16;
    const int a_sz = (row0 + srow < NN) ? 16 : 0;
    const unsigned st_off = srow * 80 + scol * 2;
    auto ldAB = [&](int s, int kt) {
#pragma unroll
        for (int p = 0; p < 2; p++) {
            const unsigned da = As_sh + s * STG_B + st_off + p * 16;
            const __half* sa = g_feat_h + (size_t)(row0 + srow) * FF + kt + scol + p * 8;
            asm volatile("cp.async.ca.shared.global [%0], [%1], 16, %2;"
                         :: "r"(da), "l"(sa), "r"(a_sz));
            const unsigned db = Bs_sh + s * STG_B + st_off + p * 16;
            const __half* sb = g_WhT + (size_t)srow * FF + kt + scol + p * 8;
            asm volatile("cp.async.ca.shared.global [%0], [%1], 16;"
                         :: "r"(db), "l"(sb));
        }
    };

    unsigned a_off[2];
#pragma unroll
    for (int mt = 0; mt < 2; mt++) {
        const unsigned r  = wm * 32 + mt * 16 + (lane & 15);
        const unsigned cc = (lane >> 4) * 8;
        a_off[mt] = r * 80 + cc * 2;
    }
    unsigned b_off[4];
#pragma unroll
    for (int ntp = 0; ntp < 4; ntp++) {
        const unsigned r  = wn * 64 + ntp * 16 + (lane & 7) + ((lane >> 4) << 3);
        const unsigned cc = ((lane >> 3) & 1) * 8;
        b_off[ntp] = r * 80 + cc * 2;
    }

    // 3-stage prologue: 2 chunks in flight
    ldAB(0, 0);
    asm volatile("cp.async.commit_group;");
    ldAB(1, 32);
    asm volatile("cp.async.commit_group;");

    int cur = 0;
    for (int it = 0; it < FF / 32; it++) {
        if (it < FF / 32 - 1) {
            asm volatile("cp.async.wait_group 1;");
        } else {
            asm volatile("cp.async.wait_group 0;");
        }
        __syncthreads();
        if (it + 2 < FF / 32) {
            int nstage = cur + 2;
            if (nstage >= 3) nstage -= 3;
            ldAB(nstage, (it + 2) * 32);
            asm volatile("cp.async.commit_group;");
        }
#pragma unroll
        for (int kk = 0; kk < 32; kk += 16) {
            unsigned a[2][4];
#pragma unroll
            for (int mt = 0; mt < 2; mt++) {
                const unsigned addr = As_sh + cur * STG_B + a_off[mt] + kk * 2;
                asm volatile("ldmatrix.sync.aligned.m8n8.x4.shared.b16 {%0,%1,%2,%3}, [%4];"
                             : "=r"(a[mt][0]), "=r"(a[mt][1]), "=r"(a[mt][2]), "=r"(a[mt][3])
                             : "r"(addr));
            }
#pragma unroll
            for (int ntp = 0; ntp < 4; ntp++) {
                unsigned b0e, b1e, b0o, b1o;
                const unsigned addr = Bs_sh + cur * STG_B + b_off[ntp] + kk * 2;
                asm volatile("ldmatrix.sync.aligned.m8n8.x4.shared.b16 {%0,%1,%2,%3}, [%4];"
                             : "=r"(b0e), "=r"(b1e), "=r"(b0o), "=r"(b1o)
                             : "r"(addr));
#pragma unroll
                for (int mt = 0; mt < 2; mt++) {
                    asm volatile(
                        "mma.sync.aligned.m16n8k16.row.col.f32.f16.f16.f32 "
                        "{%0,%1,%2,%3}, {%4,%5,%6,%7}, {%8,%9}, {%0,%1,%2,%3};"
                        : "+f"(c[mt][ntp * 2][0]), "+f"(c[mt][ntp * 2][1]),
                          "+f"(c[mt][ntp * 2][2]), "+f"(c[mt][ntp * 2][3])
                        : "r"(a[mt][0]), "r"(a[mt][1]), "r"(a[mt][2]), "r"(a[mt][3]),
                          "r"(b0e), "r"(b1e));
                    asm volatile(
                        "mma.sync.aligned.m16n8k16.row.col.f32.f16.f16.f32 "
                        "{%0,%1,%2,%3}, {%4,%5,%6,%7}, {%8,%9}, {%0,%1,%2,%3};"
                        : "+f"(c[mt][ntp * 2 + 1][0]), "+f"(c[mt][ntp * 2 + 1][1]),
                          "+f"(c[mt][ntp * 2 + 1][2]), "+f"(c[mt][ntp * 2 + 1][3])
                        : "r"(a[mt][0]), "r"(a[mt][1]), "r"(a[mt][2]), "r"(a[mt][3]),
                          "r"(b0o), "r"(b1o));
                }
            }
        }
        if (++cur == 3) cur = 0;
    }

    // epilogue: bias + attribute mix, fp16 flow store, partial score -> smem atomics
#pragma unroll
    for (int mt = 0; mt < 2; mt++) {
        const int rl1 = wm * 32 + mt * 16 + gid;
        const int rl2 = rl1 + 8;
        const int r1 = row0 + rl1, r2 = row0 + rl2;
        float a0r1 = 0.f, a1r1 = 0.f, a0r2 = 0.f, a1r2 = 0.f;
        if (r1 < NN) { a0r1 = adj[r1]; a1r1 = adj[NN + r1]; }
        if (r2 < NN) { a0r2 = adj[r2]; a1r2 = adj[NN + r2]; }
        float s1 = 0.f, s2 = 0.f;
#pragma unroll
        for (int nt = 0; nt < 8; nt++) {
            const int col = wn * 64 + nt * 8 + tig * 2;
            const float ch0a = ch_s0[col], ch0b = ch_s0[col + 1];
            const float ch1a = ch_s1[col], ch1b = ch_s1[col + 1];
            const float ba = bias_s[col], bbv = bias_s[col + 1];
            const float v1a = 0.5f * (c[mt][nt][0] + ba  + a0r1 * ch0a + a1r1 * ch1a);
            const float v1b = 0.5f * (c[mt][nt][1] + bbv + a0r1 * ch0b + a1r1 * ch1b);
            const float v2a = 0.5f * (c[mt][nt][2] + ba  + a0r2 * ch0a + a1r2 * ch1a);
            const float v2b = 0.5f * (c[mt][nt][3] + bbv + a0r2 * ch0b + a1r2 * ch1b);
            if (r1 < NN)
                *(__half2*)&g_flow_h[(size_t)r1 * DD + col] = __floats2half2_rn(v1a, v1b);
            if (r2 < NN)
                *(__half2*)&g_flow_h[(size_t)r2 * DD + col] = __floats2half2_rn(v2a, v2b);
            s1 += v1a * att_s[col] + v1b * att_s[col + 1];
            s2 += v2a * att_s[col] + v2b * att_s[col + 1];
        }
        s1 += __shfl_xor_sync(0xffffffffu, s1, 1);
        s1 += __shfl_xor_sync(0xffffffffu, s1, 2);
        s2 += __shfl_xor_sync(0xffffffffu, s2, 1);
        s2 += __shfl_xor_sync(0xffffffffu, s2, 2);
        if (tig == 0) {
            atomicAdd(&sc[rl1], s1);
            atomicAdd(&sc[rl2], s2);
        }
    }
    __syncthreads();
    if (tid < 128) {
        const int r = row0 + tid;
        if (r < NN) g_score[r] = sc[tid] + att1b[0];
    }
}

// ---------------- K3: at / bb halves of the character GEMV (k-split x4) ---------------
__global__ __launch_bounds__(128) void lat_kernel2() {
    __shared__ float ch[32];
    const int t  = blockIdx.x >> 2;
    const int k0 = (blockIdx.x & 3) * 32;
    const int d  = threadIdx.x;
    const float* Wc = g_ptrs.wchar;
    const int m = (t < 2) ? t : (t - 2);
    if (d < 32) ch[d] = g_char[m * DD + k0 + d];
    __syncthreads();
    float s = 0.f;
    if (t < 2) {
#pragma unroll
        for (int i = 0; i < 32; i++) s += ch[i] * Wc[(size_t)(k0 + i) * DD + d];
        atomicAdd(&g_at[t * DD + d], s);
    } else {
#pragma unroll
        for (int i = 0; i < 32; i++) s += ch[i] * Wc[(size_t)(DD + k0 + i) * DD + d];
        atomicAdd(&g_bb[m * DD + d], s);
    }
}

// ---------------- K6: per-row gather + softmax + weighted sum -> fp16 agg ---------------
__global__ __launch_bounds__(256) void agg_kernel(const int* __restrict__ history) {
    const int warp = threadIdx.x >> 5, lane = threadIdx.x & 31;
    const int b = blockIdx.x * 8 + warp;
    const int h = history[b * KK + lane];
    const float s = g_score[h];
    float mx = s;
#pragma unroll
    for (int o = 16; o; o >>= 1) mx = fmaxf(mx, __shfl_xor_sync(0xffffffffu, mx, o));
    const float e = expf(s - mx);
    float sum = e;
#pragma unroll
    for (int o = 16; o; o >>= 1) sum += __shfl_xor_sync(0xffffffffu, sum, o);
    const float att = e / sum;
    float4 acc = make_float4(0.f, 0.f, 0.f, 0.f);
    const uint2* fa = (const uint2*)g_flow_h;
#pragma unroll
    for (int k = 0; k < KK; k++) {
        const int   idx = __shfl_sync(0xffffffffu, h, k);
        const float w   = __shfl_sync(0xffffffffu, att, k);
        const uint2 f = fa[idx * 32 + lane];
        const float2 p0 = __half22float2(*(const __half2*)&f.x);
        const float2 p1 = __half22float2(*(const __half2*)&f.y);
        acc.x += w * p0.x; acc.y += w * p0.y; acc.z += w * p1.x; acc.w += w * p1.y;
    }
    __half2 h0 = __floats2half2_rn(acc.x, acc.y);
    __half2 h1 = __floats2half2_rn(acc.z, acc.w);
    uint2 st;
    st.x = *(unsigned*)&h0;
    st.y = *(unsigned*)&h1;
    *(uint2*)&g_agg_h[(size_t)b * DD + lane * 4] = st;
}

// ---------------- K7: fp16 tensor out-GEMM + fused sigmoid-Lat + relu/Lat-dot -----------
__global__ __launch_bounds__(256) void outpred_kernel(const float* __restrict__ lin1b,
                                                      float* __restrict__ out) {
    __shared__ __half As[128][40];
    __shared__ __half Bs[128][40];
    __shared__ float Lat_s[2 * MM * DD];
    __shared__ float lb_s[DD];
    const int*   catr = g_ptrs.catr;
    const int*   catn = g_ptrs.catn;
    const int*   pav  = g_ptrs.pa;
    const int tid  = threadIdx.x;
    const int warp = tid >> 5, lane = tid & 31;
    const int gid  = lane >> 2, tig = lane & 3;
    const int row0 = blockIdx.x * 128;
    for (int i = tid; i < 2 * MM * DD; i += 256) {
        const int d  = i & 127;
        const int p  = (i >> 7) % MM;
        const int cc = i / (MM * DD);
        Lat_s[i] = 1.f / (1.f + expf(-(g_at[cc * DD + d] + g_bb[p * DD + d])));
    }
    if (tid < DD) lb_s[tid] = lin1b[tid];

    float c[16][4];
#pragma unroll
    for (int nt = 0; nt < 16; nt++)
#pragma unroll
        for (int j = 0; j < 4; j++) c[nt][j] = 0.f;

    const int arow = tid >> 1;
    const int acol = (tid & 1) * 16;
#pragma unroll
    for (int kt = 0; kt < DD; kt += 32) {
        *(uint4*)&As[arow][acol]     = *(const uint4*)&g_agg_h[(size_t)(row0 + arow) * DD + kt + acol];
        *(uint4*)&As[arow][acol + 8] = *(const uint4*)&g_agg_h[(size_t)(row0 + arow) * DD + kt + acol + 8];
        *(uint4*)&Bs[arow][acol]     = *(const uint4*)&g_W1hT[(size_t)arow * DD + kt + acol];
        *(uint4*)&Bs[arow][acol + 8] = *(const uint4*)&g_W1hT[(size_t)arow * DD + kt + acol + 8];
        __syncthreads();
#pragma unroll
        for (int kk = 0; kk < 32; kk += 16) {
            const unsigned a0 = *(const unsigned*)&As[warp * 16 + gid    ][kk + tig * 2];
            const unsigned a1 = *(const unsigned*)&As[warp * 16 + gid + 8][kk + tig * 2];
            const unsigned a2 = *(const unsigned*)&As[warp * 16 + gid    ][kk + tig * 2 + 8];
            const unsigned a3 = *(const unsigned*)&As[warp * 16 + gid + 8][kk + tig * 2 + 8];
#pragma unroll
            for (int nt = 0; nt < 16; nt++) {
                const unsigned b0 = *(const unsigned*)&Bs[nt * 8 + gid][kk + tig * 2];
                const unsigned b1 = *(const unsigned*)&Bs[nt * 8 + gid][kk + tig * 2 + 8];
                asm volatile(
                    "mma.sync.aligned.m16n8k16.row.col.f32.f16.f16.f32 "
                    "{%0,%1,%2,%3}, {%4,%5,%6,%7}, {%8,%9}, {%0,%1,%2,%3};"
                    : "+f"(c[nt][0]), "+f"(c[nt][1]), "+f"(c[nt][2]), "+f"(c[nt][3])
                    : "r"(a0), "r"(a1), "r"(a2), "r"(a3), "r"(b0), "r"(b1));
            }
        }
        __syncthreads();
    }

    const int r1 = row0 + warp * 16 + gid;
    const int r2 = r1 + 8;
    const int p1_ = pav[r1], p2_ = pav[r2];
    const float* Lr1 = &Lat_s[(catr[r1] * MM + p1_) * DD];
    const float* Ln1 = &Lat_s[(catn[r1] * MM + p1_) * DD];
    const float* Lr2 = &Lat_s[(catr[r2] * MM + p2_) * DD];
    const float* Ln2 = &Lat_s[(catn[r2] * MM + p2_) * DD];
    float sr1 = 0.f, sn1 = 0.f, sr2 = 0.f, sn2 = 0.f;
#pragma unroll
    for (int nt = 0; nt < 16; nt++) {
        const int col = nt * 8 + tig * 2;
        const float b0 = lb_s[col], b1 = lb_s[col + 1];
        const float o0 = fmaxf(c[nt][0] + b0, 0.f);
        const float o1 = fmaxf(c[nt][1] + b1, 0.f);
        const float o2 = fmaxf(c[nt][2] + b0, 0.f);
        const float o3 = fmaxf(c[nt][3] + b1, 0.f);
        sr1 += o0 * Lr1[col] + o1 * Lr1[col + 1];
        sn1 += o0 * Ln1[col] + o1 * Ln1[col + 1];
        sr2 += o2 * Lr2[col] + o3 * Lr2[col + 1];
        sn2 += o2 * Ln2[col] + o3 * Ln2[col + 1];
    }
#pragma unroll
    for (int o = 1; o < 4; o <<= 1) {
        sr1 += __shfl_xor_sync(0xffffffffu, sr1, o);
        sn1 += __shfl_xor_sync(0xffffffffu, sn1, o);
        sr2 += __shfl_xor_sync(0xffffffffu, sr2, o);
        sn2 += __shfl_xor_sync(0xffffffffu, sn2, o);
    }
    if (tig == 0) {
        out[r1]      = sr1;
        out[BB + r1] = sn1;
        out[r2]      = sr2;
        out[BB + r2] = sn2;
    }
}

// ---------------- host ----------------
extern "C" void kernel_launch(void* const* d_in, const int* in_sizes, int n_in,
                              void* d_out, int out_size) {
    const float* feat = nullptr;
    const float* adj  = nullptr;
    const int*   hist = nullptr;
    const float* b1   = nullptr;
    const void*  s32[8] = {nullptr};
    int n32 = 0;
    const float* s128[4] = {nullptr};
    int n128 = 0;

    for (int i = 0; i < n_in; i++) {
        const int sz = in_sizes[i];
        if (sz == NN * FF)      feat = (const float*)d_in[i];
        else if (sz == MM * NN) adj  = (const float*)d_in[i];
        else if (sz == BB * KK) hist = (const int*)d_in[i];
        else if (sz == BB)      { if (n32 < 8)  s32[n32++]  = d_in[i]; }
        else if (sz == DD)      { if (n128 < 4) s128[n128++] = (const float*)d_in[i]; }
        else if (sz == 1)       b1 = (const float*)d_in[i];
    }
    const float* bemb  = s128[0];
    const float* att1w = s128[1];
    const float* lin1b = s128[2];

    cudaFuncSetAttribute(gemm_fused, cudaFuncAttributeMaxDynamicSharedMemorySize,
                         GEMM_SMEM);

    probe_kernel<<<1, 32>>>(s32[0], s32[1], s32[2], s32[3], s32[4], s32[5], s32[6]);
    zero_kernel<<<1, 256>>>();
    wcvt_kernel<<<(FF * DD + DD * DD + 255) / 256, 256>>>(s32[0], s32[2], s32[4], s32[6]);
    adjfeat_kernel<<<(NN + 255) / 256, 256>>>(adj, feat);   // slot #3 -> profiled
    char_kernel2<<<MM * 8, 128>>>(bemb);
    gemm_fused<<<(NN + 127) / 128, 256, GEMM_SMEM>>>(bemb, adj, att1w, b1);
    lat_kernel2<<<(MM + 2) * 4, 128>>>();
    agg_kernel<<<BB / 8, 256>>>(hist);
    outpred_kernel<<<BB / 128, 256>>>(lin1b, (float*)d_out);
}

// round 16
// speedup vs baseline: 1.0817x; 1.0344x over previous
#include <cuda_runtime.h>
#include <cuda_fp16.h>

#define NN 100000
#define FF 256
#define DD 128
#define MM 10
#define BB 32768
#define KK 32

// ---------------- scratch (device globals; no allocation) ----------------
__device__ __align__(16) __half g_feat_h[NN * FF];    // 51.2 MB feature fp16
__device__ __align__(16) __half g_WhT[DD * FF];       // Wemb transposed [n][k] fp16
__device__ __align__(16) __half g_W1hT[DD * DD];      // (W1_top+W1_bot) transposed [n][k] fp16
__device__ __align__(16) __half g_flow_h[NN * DD];    // 25.6 MB flow_all fp16
__device__ __align__(16) __half g_agg_h[BB * DD];     // 8 MB agg fp16
__device__ float g_score[NN];
__device__ __align__(16) float g_char[MM * DD];
__device__ __align__(16) float g_cefeat[MM * FF];
__device__ float g_rowsum[MM];
__device__ __align__(16) float g_at[2 * DD];
__device__ __align__(16) float g_bb[MM * DD];

struct Ptrs {
    const float* wemb;
    const float* wchar;
    const float* lin1w;
    const int*   catr;
    const int*   catn;
    const int*   pa;
};
__device__ Ptrs g_ptrs;

// ---------------- K0: probe + zero + weight conversion (merged, R13 WIN form) ----------
__global__ void fixup2_kernel(const void* s0, const void* s1, const void* s2,
                              const void* s3, const void* s4, const void* s5,
                              const void* s6) {
    const unsigned* u = (const unsigned*)s0;
    bool intlike = true;
    for (int i = 0; i < 64; i++) {
        if (u[i] >= 100000u) { intlike = false; break; }
    }
    const float* wemb  = intlike ? (const float*)s4 : (const float*)s0;
    const float* lin1w = intlike ? (const float*)s6 : (const float*)s2;
    const int b = blockIdx.x, t = threadIdx.x;
    if (b == 192) {
        if (t == 0) {
            Ptrs p;
            if (intlike) {
                p.catr = (const int*)s1;  p.catn = (const int*)s2;  p.pa = (const int*)s3;
                p.wemb = (const float*)s4; p.wchar = (const float*)s5; p.lin1w = (const float*)s6;
            } else {
                p.wemb = (const float*)s0; p.wchar = (const float*)s1; p.lin1w = (const float*)s2;
                p.catr = (const int*)s4;  p.catn = (const int*)s5;  p.pa = (const int*)s6;
            }
            g_ptrs = p;
        }
        for (int i = t; i < MM * FF; i += 256) g_cefeat[i] = 0.f;
        for (int i = t; i < MM * DD; i += 256) { g_char[i] = 0.f; g_bb[i] = 0.f; }
        for (int i = t; i < 2 * DD; i += 256) g_at[i] = 0.f;
        if (t < MM) g_rowsum[t] = 0.f;
    } else {
        const int i = b * 256 + t;
        if (i < FF * DD) {
            const int k = i / DD, n = i % DD;
            g_WhT[n * FF + k] = __float2half(wemb[i]);
        } else {
            const int j = i - FF * DD;
            const int k = j / DD, n = j % DD;
            g_W1hT[n * DD + k] = __float2half(lin1w[k * DD + n] + lin1w[(DD + k) * DD + n]);
        }
    }
}

// ---------------- K1: adj@feature + rowsum + fp16 copy (R15 WIN: MLP-16) ----------------
__global__ __launch_bounds__(256) void adjfeat_kernel(const float* __restrict__ adj,
                                                      const float* __restrict__ feat) {
    __shared__ float adj_s[MM][256];
    const int n0  = blockIdx.x * 256;
    const int tid = threadIdx.x;
    int limit = NN - n0;
    if (limit > 256) limit = 256;
    for (int m = 0; m < MM; m++)
        if (tid < limit) adj_s[m][tid] = adj[(size_t)m * NN + n0 + tid];
    __syncthreads();
    float acc[MM];
#pragma unroll
    for (int m = 0; m < MM; m++) acc[m] = 0.f;
    int j = 0;
    for (; j + 16 <= limit; j += 16) {
        float v[16];
#pragma unroll
        for (int u = 0; u < 16; u++)
            v[u] = feat[(size_t)(n0 + j + u) * FF + tid];
#pragma unroll
        for (int u = 0; u < 16; u++)
            g_feat_h[(size_t)(n0 + j + u) * FF + tid] = __float2half(v[u]);
#pragma unroll
        for (int u = 0; u < 16; u++)
#pragma unroll
            for (int m = 0; m < MM; m++) acc[m] += adj_s[m][j + u] * v[u];
    }
    for (; j < limit; j++) {
        const float v = feat[(size_t)(n0 + j) * FF + tid];
        g_feat_h[(size_t)(n0 + j) * FF + tid] = __float2half(v);
#pragma unroll
        for (int m = 0; m < MM; m++) acc[m] += adj_s[m][j] * v;
    }
#pragma unroll
    for (int m = 0; m < MM; m++) atomicAdd(&g_cefeat[m * FF + tid], acc[m]);
    const int warp = tid >> 5, lane = tid & 31;
    for (int m = warp; m < MM; m += 8) {
        float s = 0.f;
        for (int jj = lane; jj < limit; jj += 32) s += adj_s[m][jj];
#pragma unroll
        for (int o = 16; o; o >>= 1) s += __shfl_xor_sync(0xffffffffu, s, o);
        if (lane == 0) atomicAdd(&g_rowsum[m], s);
    }
}

// ---------------- K2: char[m][d] += ce_feat[m][k0:k0+32] @ W[k0:k0+32, d] ---------------
__global__ __launch_bounds__(128) void char_kernel2(const float* __restrict__ bias) {
    __shared__ float ce[32];
    const int m  = blockIdx.x >> 3;
    const int k0 = (blockIdx.x & 7) * 32;
    const int d  = threadIdx.x;
    if (d < 32) ce[d] = g_cefeat[m * FF + k0 + d];
    __syncthreads();
    const float* W = g_ptrs.wemb;
    float s = 0.f;
#pragma unroll
    for (int k = 0; k < 32; k++) s += ce[k] * W[(size_t)(k0 + k) * DD + d];
    if (k0 == 0) s += g_rowsum[m] * bias[d];
    atomicAdd(&g_char[m * DD + d], s);
}

// ---------------- K5: fp16 tensor GEMM, 3-stage pipeline (R13 WIN form) ----------------
#define STG_B (128 * 40 * 2)   // one stage of A or B: 10240 bytes
#define GEMM_SMEM (6 * STG_B + 640 * 4)
__global__ __launch_bounds__(256) void gemm_fused(const float* __restrict__ bias,
                                                  const float* __restrict__ adj,
                                                  const float* __restrict__ att1w,
                                                  const float* __restrict__ att1b) {
    extern __shared__ __align__(16) char dsm[];
    float* att_s  = (float*)(dsm + 6 * STG_B);
    float* bias_s = att_s + DD;
    float* ch_s0  = bias_s + DD;
    float* ch_s1  = ch_s0 + DD;
    float* sc     = ch_s1 + DD;
    const int tid  = threadIdx.x;
    const int warp = tid >> 5, lane = tid & 31;
    const int gid  = lane >> 2, tig = lane & 3;
    const int wm   = warp & 3, wn = warp >> 2;     // 4 m-warps x 2 n-warps
    const int row0 = blockIdx.x * 128;
    if (tid < DD) {
        att_s[tid]  = att1w[tid];
        bias_s[tid] = bias[tid];
        ch_s0[tid]  = g_char[tid];
        ch_s1[tid]  = g_char[DD + tid];
        sc[tid]     = 0.f;
    }

    float c[2][8][4];
#pragma unroll
    for (int mt = 0; mt < 2; mt++)
#pragma unroll
        for (int nt = 0; nt < 8; nt++)
#pragma unroll
            for (int j = 0; j < 4; j++) c[mt][nt][j] = 0.f;

    const unsigned As_sh = (unsigned)__cvta_generic_to_shared(dsm);
    const unsigned Bs_sh = As_sh + 3 * STG_B;
    const int srow = tid >> 1;
    const int scol = (tid & 1) * 16;
    const int a_sz = (row0 + srow < NN) ? 16 : 0;
    const unsigned st_off = srow * 80 + scol * 2;
    auto ldAB = [&](int s, int kt) {
#pragma unroll
        for (int p = 0; p < 2; p++) {
            const unsigned da = As_sh + s * STG_B + st_off + p * 16;
            const __half* sa = g_feat_h + (size_t)(row0 + srow) * FF + kt + scol + p * 8;
            asm volatile("cp.async.ca.shared.global [%0], [%1], 16, %2;"
                         :: "r"(da), "l"(sa), "r"(a_sz));
            const unsigned db = Bs_sh + s * STG_B + st_off + p * 16;
            const __half* sb = g_WhT + (size_t)srow * FF + kt + scol + p * 8;
            asm volatile("cp.async.ca.shared.global [%0], [%1], 16;"
                         :: "r"(db), "l"(sb));
        }
    };

    unsigned a_off[2];
#pragma unroll
    for (int mt = 0; mt < 2; mt++) {
        const unsigned r  = wm * 32 + mt * 16 + (lane & 15);
        const unsigned cc = (lane >> 4) * 8;
        a_off[mt] = r * 80 + cc * 2;
    }
    unsigned b_off[4];
#pragma unroll
    for (int ntp = 0; ntp < 4; ntp++) {
        const unsigned r  = wn * 64 + ntp * 16 + (lane & 7) + ((lane >> 4) << 3);
        const unsigned cc = ((lane >> 3) & 1) * 8;
        b_off[ntp] = r * 80 + cc * 2;
    }

    // 3-stage prologue: 2 chunks in flight
    ldAB(0, 0);
    asm volatile("cp.async.commit_group;");
    ldAB(1, 32);
    asm volatile("cp.async.commit_group;");

    int cur = 0;
    for (int it = 0; it < FF / 32; it++) {
        if (it < FF / 32 - 1) {
            asm volatile("cp.async.wait_group 1;");
        } else {
            asm volatile("cp.async.wait_group 0;");
        }
        __syncthreads();
        if (it + 2 < FF / 32) {
            int nstage = cur + 2;
            if (nstage >= 3) nstage -= 3;
            ldAB(nstage, (it + 2) * 32);
            asm volatile("cp.async.commit_group;");
        }
#pragma unroll
        for (int kk = 0; kk < 32; kk += 16) {
            unsigned a[2][4];
#pragma unroll
            for (int mt = 0; mt < 2; mt++) {
                const unsigned addr = As_sh + cur * STG_B + a_off[mt] + kk * 2;
                asm volatile("ldmatrix.sync.aligned.m8n8.x4.shared.b16 {%0,%1,%2,%3}, [%4];"
                             : "=r"(a[mt][0]), "=r"(a[mt][1]), "=r"(a[mt][2]), "=r"(a[mt][3])
                             : "r"(addr));
            }
#pragma unroll
            for (int ntp = 0; ntp < 4; ntp++) {
                unsigned b0e, b1e, b0o, b1o;
                const unsigned addr = Bs_sh + cur * STG_B + b_off[ntp] + kk * 2;
                asm volatile("ldmatrix.sync.aligned.m8n8.x4.shared.b16 {%0,%1,%2,%3}, [%4];"
                             : "=r"(b0e), "=r"(b1e), "=r"(b0o), "=r"(b1o)
                             : "r"(addr));
#pragma unroll
                for (int mt = 0; mt < 2; mt++) {
                    asm volatile(
                        "mma.sync.aligned.m16n8k16.row.col.f32.f16.f16.f32 "
                        "{%0,%1,%2,%3}, {%4,%5,%6,%7}, {%8,%9}, {%0,%1,%2,%3};"
                        : "+f"(c[mt][ntp * 2][0]), "+f"(c[mt][ntp * 2][1]),
                          "+f"(c[mt][ntp * 2][2]), "+f"(c[mt][ntp * 2][3])
                        : "r"(a[mt][0]), "r"(a[mt][1]), "r"(a[mt][2]), "r"(a[mt][3]),
                          "r"(b0e), "r"(b1e));
                    asm volatile(
                        "mma.sync.aligned.m16n8k16.row.col.f32.f16.f16.f32 "
                        "{%0,%1,%2,%3}, {%4,%5,%6,%7}, {%8,%9}, {%0,%1,%2,%3};"
                        : "+f"(c[mt][ntp * 2 + 1][0]), "+f"(c[mt][ntp * 2 + 1][1]),
                          "+f"(c[mt][ntp * 2 + 1][2]), "+f"(c[mt][ntp * 2 + 1][3])
                        : "r"(a[mt][0]), "r"(a[mt][1]), "r"(a[mt][2]), "r"(a[mt][3]),
                          "r"(b0o), "r"(b1o));
                }
            }
        }
        if (++cur == 3) cur = 0;
    }

    // epilogue: bias + attribute mix, fp16 flow store, partial score -> smem atomics
#pragma unroll
    for (int mt = 0; mt < 2; mt++) {
        const int rl1 = wm * 32 + mt * 16 + gid;
        const int rl2 = rl1 + 8;
        const int r1 = row0 + rl1, r2 = row0 + rl2;
        float a0r1 = 0.f, a1r1 = 0.f, a0r2 = 0.f, a1r2 = 0.f;
        if (r1 < NN) { a0r1 = adj[r1]; a1r1 = adj[NN + r1]; }
        if (r2 < NN) { a0r2 = adj[r2]; a1r2 = adj[NN + r2]; }
        float s1 = 0.f, s2 = 0.f;
#pragma unroll
        for (int nt = 0; nt < 8; nt++) {
            const int col = wn * 64 + nt * 8 + tig * 2;
            const float ch0a = ch_s0[col], ch0b = ch_s0[col + 1];
            const float ch1a = ch_s1[col], ch1b = ch_s1[col + 1];
            const float ba = bias_s[col], bbv = bias_s[col + 1];
            const float v1a = 0.5f * (c[mt][nt][0] + ba  + a0r1 * ch0a + a1r1 * ch1a);
            const float v1b = 0.5f * (c[mt][nt][1] + bbv + a0r1 * ch0b + a1r1 * ch1b);
            const float v2a = 0.5f * (c[mt][nt][2] + ba  + a0r2 * ch0a + a1r2 * ch1a);
            const float v2b = 0.5f * (c[mt][nt][3] + bbv + a0r2 * ch0b + a1r2 * ch1b);
            if (r1 < NN)
                *(__half2*)&g_flow_h[(size_t)r1 * DD + col] = __floats2half2_rn(v1a, v1b);
            if (r2 < NN)
                *(__half2*)&g_flow_h[(size_t)r2 * DD + col] = __floats2half2_rn(v2a, v2b);
            s1 += v1a * att_s[col] + v1b * att_s[col + 1];
            s2 += v2a * att_s[col] + v2b * att_s[col + 1];
        }
        s1 += __shfl_xor_sync(0xffffffffu, s1, 1);
        s1 += __shfl_xor_sync(0xffffffffu, s1, 2);
        s2 += __shfl_xor_sync(0xffffffffu, s2, 1);
        s2 += __shfl_xor_sync(0xffffffffu, s2, 2);
        if (tig == 0) {
            atomicAdd(&sc[rl1], s1);
            atomicAdd(&sc[rl2], s2);
        }
    }
    __syncthreads();
    if (tid < 128) {
        const int r = row0 + tid;
        if (r < NN) g_score[r] = sc[tid] + att1b[0];
    }
}

// ---------------- K3: at / bb halves of the character GEMV (k-split x4) ---------------
__global__ __launch_bounds__(128) void lat_kernel2() {
    __shared__ float ch[32];
    const int t  = blockIdx.x >> 2;
    const int k0 = (blockIdx.x & 3) * 32;
    const int d  = threadIdx.x;
    const float* Wc = g_ptrs.wchar;
    const int m = (t < 2) ? t : (t - 2);
    if (d < 32) ch[d] = g_char[m * DD + k0 + d];
    __syncthreads();
    float s = 0.f;
    if (t < 2) {
#pragma unroll
        for (int i = 0; i < 32; i++) s += ch[i] * Wc[(size_t)(k0 + i) * DD + d];
        atomicAdd(&g_at[t * DD + d], s);
    } else {
#pragma unroll
        for (int i = 0; i < 32; i++) s += ch[i] * Wc[(size_t)(DD + k0 + i) * DD + d];
        atomicAdd(&g_bb[m * DD + d], s);
    }
}

// ---------------- K6: per-row gather + softmax + weighted sum -> fp16 agg ---------------
__global__ __launch_bounds__(256) void agg_kernel(const int* __restrict__ history) {
    const int warp = threadIdx.x >> 5, lane = threadIdx.x & 31;
    const int b = blockIdx.x * 8 + warp;
    const int h = history[b * KK + lane];
    const float s = g_score[h];
    float mx = s;
#pragma unroll
    for (int o = 16; o; o >>= 1) mx = fmaxf(mx, __shfl_xor_sync(0xffffffffu, mx, o));
    const float e = expf(s - mx);
    float sum = e;
#pragma unroll
    for (int o = 16; o; o >>= 1) sum += __shfl_xor_sync(0xffffffffu, sum, o);
    const float att = e / sum;
    float4 acc = make_float4(0.f, 0.f, 0.f, 0.f);
    const uint2* fa = (const uint2*)g_flow_h;
#pragma unroll
    for (int k = 0; k < KK; k++) {
        const int   idx = __shfl_sync(0xffffffffu, h, k);
        const float w   = __shfl_sync(0xffffffffu, att, k);
        const uint2 f = fa[idx * 32 + lane];
        const float2 p0 = __half22float2(*(const __half2*)&f.x);
        const float2 p1 = __half22float2(*(const __half2*)&f.y);
        acc.x += w * p0.x; acc.y += w * p0.y; acc.z += w * p1.x; acc.w += w * p1.y;
    }
    __half2 h0 = __floats2half2_rn(acc.x, acc.y);
    __half2 h1 = __floats2half2_rn(acc.z, acc.w);
    uint2 st;
    st.x = *(unsigned*)&h0;
    st.y = *(unsigned*)&h1;
    *(uint2*)&g_agg_h[(size_t)b * DD + lane * 4] = st;
}

// ---------------- K7: fp16 tensor out-GEMM + fused sigmoid-Lat + relu/Lat-dot -----------
__global__ __launch_bounds__(256) void outpred_kernel(const float* __restrict__ lin1b,
                                                      float* __restrict__ out) {
    __shared__ __half As[128][40];
    __shared__ __half Bs[128][40];
    __shared__ float Lat_s[2 * MM * DD];
    __shared__ float lb_s[DD];
    const int*   catr = g_ptrs.catr;
    const int*   catn = g_ptrs.catn;
    const int*   pav  = g_ptrs.pa;
    const int tid  = threadIdx.x;
    const int warp = tid >> 5, lane = tid & 31;
    const int gid  = lane >> 2, tig = lane & 3;
    const int row0 = blockIdx.x * 128;
    for (int i = tid; i < 2 * MM * DD; i += 256) {
        const int d  = i & 127;
        const int p  = (i >> 7) % MM;
        const int cc = i / (MM * DD);
        Lat_s[i] = 1.f / (1.f + expf(-(g_at[cc * DD + d] + g_bb[p * DD + d])));
    }
    if (tid < DD) lb_s[tid] = lin1b[tid];

    float c[16][4];
#pragma unroll
    for (int nt = 0; nt < 16; nt++)
#pragma unroll
        for (int j = 0; j < 4; j++) c[nt][j] = 0.f;

    const int arow = tid >> 1;
    const int acol = (tid & 1) * 16;
#pragma unroll
    for (int kt = 0; kt < DD; kt += 32) {
        *(uint4*)&As[arow][acol]     = *(const uint4*)&g_agg_h[(size_t)(row0 + arow) * DD + kt + acol];
        *(uint4*)&As[arow][acol + 8] = *(const uint4*)&g_agg_h[(size_t)(row0 + arow) * DD + kt + acol + 8];
        *(uint4*)&Bs[arow][acol]     = *(const uint4*)&g_W1hT[(size_t)arow * DD + kt + acol];
        *(uint4*)&Bs[arow][acol + 8] = *(const uint4*)&g_W1hT[(size_t)arow * DD + kt + acol + 8];
        __syncthreads();
#pragma unroll
        for (int kk = 0; kk < 32; kk += 16) {
            const unsigned a0 = *(const unsigned*)&As[warp * 16 + gid    ][kk + tig * 2];
            const unsigned a1 = *(const unsigned*)&As[warp * 16 + gid + 8][kk + tig * 2];
            const unsigned a2 = *(const unsigned*)&As[warp * 16 + gid    ][kk + tig * 2 + 8];
            const unsigned a3 = *(const unsigned*)&As[warp * 16 + gid + 8][kk + tig * 2 + 8];
#pragma unroll
            for (int nt = 0; nt < 16; nt++) {
                const unsigned b0 = *(const unsigned*)&Bs[nt * 8 + gid][kk + tig * 2];
                const unsigned b1 = *(const unsigned*)&Bs[nt * 8 + gid][kk + tig * 2 + 8];
                asm volatile(
                    "mma.sync.aligned.m16n8k16.row.col.f32.f16.f16.f32 "
                    "{%0,%1,%2,%3}, {%4,%5,%6,%7}, {%8,%9}, {%0,%1,%2,%3};"
                    : "+f"(c[nt][0]), "+f"(c[nt][1]), "+f"(c[nt][2]), "+f"(c[nt][3])
                    : "r"(a0), "r"(a1), "r"(a2), "r"(a3), "r"(b0), "r"(b1));
            }
        }
        __syncthreads();
    }

    const int r1 = row0 + warp * 16 + gid;
    const int r2 = r1 + 8;
    const int p1_ = pav[r1], p2_ = pav[r2];
    const float* Lr1 = &Lat_s[(catr[r1] * MM + p1_) * DD];
    const float* Ln1 = &Lat_s[(catn[r1] * MM + p1_) * DD];
    const float* Lr2 = &Lat_s[(catr[r2] * MM + p2_) * DD];
    const float* Ln2 = &Lat_s[(catn[r2] * MM + p2_) * DD];
    float sr1 = 0.f, sn1 = 0.f, sr2 = 0.f, sn2 = 0.f;
#pragma unroll
    for (int nt = 0; nt < 16; nt++) {
        const int col = nt * 8 + tig * 2;
        const float b0 = lb_s[col], b1 = lb_s[col + 1];
        const float o0 = fmaxf(c[nt][0] + b0, 0.f);
        const float o1 = fmaxf(c[nt][1] + b1, 0.f);
        const float o2 = fmaxf(c[nt][2] + b0, 0.f);
        const float o3 = fmaxf(c[nt][3] + b1, 0.f);
        sr1 += o0 * Lr1[col] + o1 * Lr1[col + 1];
        sn1 += o0 * Ln1[col] + o1 * Ln1[col + 1];
        sr2 += o2 * Lr2[col] + o3 * Lr2[col + 1];
        sn2 += o2 * Ln2[col] + o3 * Ln2[col + 1];
    }
#pragma unroll
    for (int o = 1; o < 4; o <<= 1) {
        sr1 += __shfl_xor_sync(0xffffffffu, sr1, o);
        sn1 += __shfl_xor_sync(0xffffffffu, sn1, o);
        sr2 += __shfl_xor_sync(0xffffffffu, sr2, o);
        sn2 += __shfl_xor_sync(0xffffffffu, sn2, o);
    }
    if (tig == 0) {
        out[r1]      = sr1;
        out[BB + r1] = sn1;
        out[r2]      = sr2;
        out[BB + r2] = sn2;
    }
}

// ---------------- host ----------------
extern "C" void kernel_launch(void* const* d_in, const int* in_sizes, int n_in,
                              void* d_out, int out_size) {
    const float* feat = nullptr;
    const float* adj  = nullptr;
    const int*   hist = nullptr;
    const float* b1   = nullptr;
    const void*  s32[8] = {nullptr};
    int n32 = 0;
    const float* s128[4] = {nullptr};
    int n128 = 0;

    for (int i = 0; i < n_in; i++) {
        const int sz = in_sizes[i];
        if (sz == NN * FF)      feat = (const float*)d_in[i];
        else if (sz == MM * NN) adj  = (const float*)d_in[i];
        else if (sz == BB * KK) hist = (const int*)d_in[i];
        else if (sz == BB)      { if (n32 < 8)  s32[n32++]  = d_in[i]; }
        else if (sz == DD)      { if (n128 < 4) s128[n128++] = (const float*)d_in[i]; }
        else if (sz == 1)       b1 = (const float*)d_in[i];
    }
    const float* bemb  = s128[0];
    const float* att1w = s128[1];
    const float* lin1b = s128[2];

    cudaFuncSetAttribute(gemm_fused, cudaFuncAttributeMaxDynamicSharedMemorySize,
                         GEMM_SMEM);

    fixup2_kernel<<<193, 256>>>(s32[0], s32[1], s32[2], s32[3], s32[4], s32[5], s32[6]);
    adjfeat_kernel<<<(NN + 255) / 256, 256>>>(adj, feat);
    char_kernel2<<<MM * 8, 128>>>(bemb);
    gemm_fused<<<(NN + 127) / 128, 256, GEMM_SMEM>>>(bemb, adj, att1w, b1);  // slot #3
    lat_kernel2<<<(MM + 2) * 4, 128>>>();
    agg_kernel<<<BB / 8, 256>>>(hist);
    outpred_kernel<<<BB / 128, 256>>>(lin1b, (float*)d_out);
}